// round 7
// baseline (speedup 1.0000x reference)
#include <cuda_runtime.h>
#include <cuda_bf16.h>
#include <cuda_fp16.h>
#include <math.h>
#include <float.h>
#include <stdint.h>

// ---------------------------------------------------------------------------
// VectorQuantizer: z[32,4096,64] fp32, codebook[1024,64] fp32
// Output (concat float32): quantized[8388608], loss, indices[131072],
//   codebook_loss, commitment_loss, perplexity, usage[1024], soft_usage[1024]
//
// k1: bf16 m16n8k16 3-term distance GEMM; codebook pre-permuted into MMA
//     fragment order so B loads are conflict-free LDS.128.
// k2: softmax/soft_usage from fp16 scratch, exact-fp32 argmin refine,
//     fused quantized gather + mse (k3 folded in), row-pipelined loads.
// ---------------------------------------------------------------------------

#define N_ROWS 131072
#define DIM    64
#define NCODES 1024
#define MT     128
#define NCHUNK 16
#define L2E    1.4426950408889634f
#define CANDF  0.98019867f   /* exp(-0.02): candidate window */

#define OFF_Q     0
#define OFF_LOSS  8388608
#define OFF_IDX   8388609
#define OFF_CBL   8519681
#define OFF_CML   8519682
#define OFF_PERP  8519683
#define OFF_USAGE 8519684
#define OFF_SOFT  8520708

// Scratch (device globals; no allocations allowed).
__device__ uint32_t g_dh[(size_t)N_ROWS * 512];    // 256 MB: fp16x2 of (d - mch)
__device__ float    g_mch[NCHUNK * N_ROWS];        // per-chunk row mins
__device__ uint32_t g_cbhi[32 * NCODES];           // bf16x2-hi, MMA-fragment order
__device__ uint32_t g_cblo[32 * NCODES];           // bf16x2-lo, MMA-fragment order
__device__ float    g_cc[NCODES];
__device__ float    g_soft[NCODES];
__device__ float    g_counts[NCODES];
__device__ float    g_sq;

// ---------------- helpers ---------------------------------------------------
__device__ __forceinline__ float ex2f(float x) {
    float y;
    asm("ex2.approx.ftz.f32 %0, %1;" : "=f"(y) : "f"(x));
    return y;
}
__device__ __forceinline__ uint32_t smem_u32(const void* p) {
    uint32_t a;
    asm("{ .reg .u64 t; cvta.to.shared.u64 t, %1; cvt.u32.u64 %0, t; }"
        : "=r"(a) : "l"(p));
    return a;
}
__device__ __forceinline__ void cp16(uint32_t dst, const void* src) {
    asm volatile("cp.async.cg.shared.global [%0], [%1], 16;"
                 :: "r"(dst), "l"(src) : "memory");
}
#define CP_COMMIT() asm volatile("cp.async.commit_group;" ::: "memory")
#define CP_WAIT1()  asm volatile("cp.async.wait_group 1;" ::: "memory")

__device__ __forceinline__ uint32_t pk_bf16x2(float a, float b) {
    __nv_bfloat16 ha = __float2bfloat16(a);
    __nv_bfloat16 hb = __float2bfloat16(b);
    return ((uint32_t)__bfloat16_as_ushort(hb) << 16) | __bfloat16_as_ushort(ha);
}
__device__ __forceinline__ float bf16_round(float a) {
    return __bfloat162float(__float2bfloat16(a));
}
__device__ __forceinline__ uint32_t pk_f16x2(float a, float b) {
    __half2 h = __floats2half2_rn(a, b);
    return *reinterpret_cast<uint32_t*>(&h);
}

#define MMAB(d, a, b0_, b1_) \
    asm volatile("mma.sync.aligned.m16n8k16.row.col.f32.bf16.bf16.f32 " \
        "{%0,%1,%2,%3}, {%4,%5,%6,%7}, {%8,%9}, {%0,%1,%2,%3};" \
        : "+f"((d)[0]), "+f"((d)[1]), "+f"((d)[2]), "+f"((d)[3]) \
        : "r"((a)[0]), "r"((a)[1]), "r"((a)[2]), "r"((a)[3]), \
          "r"(b0_), "r"(b1_))

// ---------------------------------------------------------------------------
// k0: codebook -> MMA-fragment-ordered bf16 hi/lo + cc + zero accumulators.
// Fragment order per chunk (2048 u32): idx = ((kc*2+kk)*2+grp)*128 + l*4 + j
//   where value = pair(k = 2*(kc*8 + (l&3) + kk*4)) of code
//   n = ch*64 + (l>>2) + (grp*4 + j)*8.
// ---------------------------------------------------------------------------
__global__ void k0_init(const float* __restrict__ cbk) {
    const int c = blockIdx.x * 256 + threadIdx.x;   // code 0..1023
    float x[64];
    const float4* p = reinterpret_cast<const float4*>(cbk + (size_t)c * DIM);
    float cs = 0.f;
#pragma unroll
    for (int i = 0; i < 16; i++) {
        float4 v = p[i];
        x[4*i+0] = v.x; x[4*i+1] = v.y; x[4*i+2] = v.z; x[4*i+3] = v.w;
        cs = fmaf(v.x, v.x, fmaf(v.y, v.y, fmaf(v.z, v.z, fmaf(v.w, v.w, cs))));
    }
    const int ch = c >> 6, nloc = c & 63;
    const int nl = nloc & 7, s = nloc >> 3, grp = s >> 2, j = s & 3;
#pragma unroll
    for (int k2 = 0; k2 < 32; k2++) {
        const int kc = k2 >> 3, qk = k2 & 7, kk = qk >> 2, q = qk & 3;
        const int l = nl * 4 + q;
        const int idx = ch * 2048 + ((kc * 2 + kk) * 2 + grp) * 128 + l * 4 + j;
        float a = x[2*k2], b = x[2*k2+1];
        float ha = bf16_round(a), hb = bf16_round(b);
        g_cbhi[idx] = pk_bf16x2(a, b);
        g_cblo[idx] = pk_bf16x2(a - ha, b - hb);
    }
    g_cc[c] = cs;
    g_soft[c] = 0.f;
    g_counts[c] = 0.f;
    if (c == 0) g_sq = 0.f;
}

// ---------------------------------------------------------------------------
// k1: bf16 3-term distance GEMM.  grid = 1024 x 256 thr, 2 CTAs/SM.
//     Warp = 16 rows x 1024 codes (16 chunks of 64).  fp16 d' + chunk mins.
// ---------------------------------------------------------------------------
__global__ void __launch_bounds__(256, 2) k1_gemm(const float* __restrict__ z) {
    __shared__ uint32_t Bs[2][2][2048];   // [buf][hi/lo][fragment-ordered chunk]
    __shared__ float cc_s[NCODES];

    const int tid = threadIdx.x;
    const int w = tid >> 5, l = tid & 31, q = l & 3, nl = l >> 2;
    const int row0 = blockIdx.x * MT;

    // prefetch chunks 0,1 (chunk ch -> buffer ch&1)
#pragma unroll
    for (int p = 0; p < 2; p++) {
        cp16(smem_u32(&Bs[p][0][tid * 4]),        g_cbhi + p * 2048 + tid * 4);
        cp16(smem_u32(&Bs[p][0][1024 + tid * 4]), g_cbhi + p * 2048 + 1024 + tid * 4);
        cp16(smem_u32(&Bs[p][1][tid * 4]),        g_cblo + p * 2048 + tid * 4);
        cp16(smem_u32(&Bs[p][1][1024 + tid * 4]), g_cblo + p * 2048 + 1024 + tid * 4);
        CP_COMMIT();
    }
    *reinterpret_cast<float4*>(&cc_s[tid * 4]) =
        *reinterpret_cast<const float4*>(g_cc + tid * 4);

    // A fragments (bf16 hi/lo) directly from global + per-row zz
    uint32_t Ah[16], Al[16];
    float zz0 = 0.f, zz1 = 0.f;
    const int r0 = row0 + w * 16 + nl, r1 = r0 + 8;
#pragma unroll
    for (int kc = 0; kc < 4; kc++) {
        const int k = kc * 16 + 2 * q;
        float2 v0 = *reinterpret_cast<const float2*>(z + (size_t)r0 * DIM + k);
        float2 v1 = *reinterpret_cast<const float2*>(z + (size_t)r1 * DIM + k);
        float2 v2 = *reinterpret_cast<const float2*>(z + (size_t)r0 * DIM + k + 8);
        float2 v3 = *reinterpret_cast<const float2*>(z + (size_t)r1 * DIM + k + 8);
        zz0 = fmaf(v0.x, v0.x, fmaf(v0.y, v0.y, fmaf(v2.x, v2.x, fmaf(v2.y, v2.y, zz0))));
        zz1 = fmaf(v1.x, v1.x, fmaf(v1.y, v1.y, fmaf(v3.x, v3.x, fmaf(v3.y, v3.y, zz1))));
        float2 vv[4] = {v0, v1, v2, v3};
#pragma unroll
        for (int i = 0; i < 4; i++) {
            float hx = bf16_round(vv[i].x), hy = bf16_round(vv[i].y);
            Ah[kc * 4 + i] = pk_bf16x2(vv[i].x, vv[i].y);
            Al[kc * 4 + i] = pk_bf16x2(vv[i].x - hx, vv[i].y - hy);
        }
    }
    zz0 += __shfl_xor_sync(0xFFFFFFFFu, zz0, 1);
    zz0 += __shfl_xor_sync(0xFFFFFFFFu, zz0, 2);
    zz1 += __shfl_xor_sync(0xFFFFFFFFu, zz1, 1);
    zz1 += __shfl_xor_sync(0xFFFFFFFFu, zz1, 2);
    __syncthreads();

#pragma unroll 1
    for (int ch = 0; ch < NCHUNK; ch++) {
        CP_WAIT1();
        __syncthreads();
        const uint32_t* BH = Bs[ch & 1][0];
        const uint32_t* BL = Bs[ch & 1][1];

        float acc[32];
#pragma unroll
        for (int i = 0; i < 32; i++) acc[i] = 0.f;

#pragma unroll
        for (int kc = 0; kc < 4; kc++) {
            const uint32_t* ah = &Ah[kc * 4];
            const uint32_t* al = &Al[kc * 4];
            const uint32_t* bh = BH + kc * 512 + l * 4;
            const uint32_t* bl = BL + kc * 512 + l * 4;
            // conflict-free LDS.128: 8 lanes/phase at 16B stride cover all banks
            uint4 h00 = *reinterpret_cast<const uint4*>(bh);         // b0 s0..3
            uint4 h01 = *reinterpret_cast<const uint4*>(bh + 128);   // b0 s4..7
            uint4 h10 = *reinterpret_cast<const uint4*>(bh + 256);   // b1 s0..3
            uint4 h11 = *reinterpret_cast<const uint4*>(bh + 384);   // b1 s4..7
            uint4 l00 = *reinterpret_cast<const uint4*>(bl);
            uint4 l01 = *reinterpret_cast<const uint4*>(bl + 128);
            uint4 l10 = *reinterpret_cast<const uint4*>(bl + 256);
            uint4 l11 = *reinterpret_cast<const uint4*>(bl + 384);
            uint32_t bh0[8] = {h00.x, h00.y, h00.z, h00.w, h01.x, h01.y, h01.z, h01.w};
            uint32_t bh1[8] = {h10.x, h10.y, h10.z, h10.w, h11.x, h11.y, h11.z, h11.w};
            uint32_t bl0[8] = {l00.x, l00.y, l00.z, l00.w, l01.x, l01.y, l01.z, l01.w};
            uint32_t bl1[8] = {l10.x, l10.y, l10.z, l10.w, l11.x, l11.y, l11.z, l11.w};
#pragma unroll
            for (int s = 0; s < 8; s++) {
                MMAB(&acc[s * 4], ah, bh0[s], bh1[s]);
                MMAB(&acc[s * 4], al, bh0[s], bh1[s]);
                MMAB(&acc[s * 4], ah, bl0[s], bl1[s]);
            }
        }
        __syncthreads();

        if (ch < NCHUNK - 2) {
            const int n0 = (ch + 2) * 2048;
            uint32_t d0 = smem_u32(&Bs[ch & 1][0][tid * 4]);
            cp16(d0,          g_cbhi + n0 + tid * 4);
            cp16(d0 + 4096u,  g_cbhi + n0 + 1024 + tid * 4);
            uint32_t d1 = smem_u32(&Bs[ch & 1][1][tid * 4]);
            cp16(d1,          g_cblo + n0 + tid * 4);
            cp16(d1 + 4096u,  g_cblo + n0 + 1024 + tid * 4);
        }
        CP_COMMIT();

        // epilogue: d = zz + cc - 2*dot; chunk mins; fp16(d - min) store
        float m0 = FLT_MAX, m1 = FLT_MAX;
#pragma unroll
        for (int s = 0; s < 8; s++) {
            float2 cv = *reinterpret_cast<const float2*>(&cc_s[ch * 64 + s * 8 + 2 * q]);
            acc[s*4+0] = fmaf(-2.f, acc[s*4+0], zz0 + cv.x);
            acc[s*4+1] = fmaf(-2.f, acc[s*4+1], zz0 + cv.y);
            acc[s*4+2] = fmaf(-2.f, acc[s*4+2], zz1 + cv.x);
            acc[s*4+3] = fmaf(-2.f, acc[s*4+3], zz1 + cv.y);
            m0 = fminf(m0, fminf(acc[s*4+0], acc[s*4+1]));
            m1 = fminf(m1, fminf(acc[s*4+2], acc[s*4+3]));
        }
        m0 = fminf(m0, __shfl_xor_sync(0xFFFFFFFFu, m0, 1));
        m0 = fminf(m0, __shfl_xor_sync(0xFFFFFFFFu, m0, 2));
        m1 = fminf(m1, __shfl_xor_sync(0xFFFFFFFFu, m1, 1));
        m1 = fminf(m1, __shfl_xor_sync(0xFFFFFFFFu, m1, 2));
        if (q == 0) {
            g_mch[ch * N_ROWS + r0] = m0;
            g_mch[ch * N_ROWS + r1] = m1;
        }
        uint32_t* o0 = g_dh + (size_t)r0 * 512 + ch * 32 + q;
        uint32_t* o1 = g_dh + (size_t)r1 * 512 + ch * 32 + q;
#pragma unroll
        for (int s = 0; s < 8; s++) {
            o0[s * 4] = pk_f16x2(acc[s*4+0] - m0, acc[s*4+1] - m0);
            o1[s * 4] = pk_f16x2(acc[s*4+2] - m1, acc[s*4+3] - m1);
        }
    }
}

// ---------------------------------------------------------------------------
// k2: Z + soft_usage + exact argmin refine + counts + indices + quantized
//     gather + mse (k3 fused).  warp-per-row, 8 rows/warp, grid = 2048 x 256.
// ---------------------------------------------------------------------------
__global__ void __launch_bounds__(256) k2_fuse(const float* __restrict__ z,
                                               const float* __restrict__ cbk,
                                               float* __restrict__ out) {
    __shared__ float soft_s[NCODES];
    __shared__ float ws[8];
    const int tid = threadIdx.x, w = tid >> 5, l = tid & 31;
    for (int i = tid; i < NCODES; i += 256) soft_s[i] = 0.f;
    __syncthreads();

    float soft_acc[32];
#pragma unroll
    for (int i = 0; i < 32; i++) soft_acc[i] = 0.f;
    float sq_acc = 0.f;

    const int rbase = blockIdx.x * 64 + w * 8;

    // preload row 0 of this warp
    float mch = (l < NCHUNK) ? g_mch[l * N_ROWS + rbase] : FLT_MAX;
    uint4 dq[4];
    {
        const uint4* rp = reinterpret_cast<const uint4*>(g_dh + (size_t)rbase * 512);
#pragma unroll
        for (int t = 0; t < 4; t++) dq[t] = rp[l + 32 * t];
    }
    float2 zrow = *reinterpret_cast<const float2*>(z + (size_t)rbase * DIM + 2 * l);

#pragma unroll 1
    for (int rr = 0; rr < 8; rr++) {
        const int row = rbase + rr;

        // issue next row's loads early (software pipeline)
        float mch_n = FLT_MAX;
        uint4 dq_n[4];
        float2 zrow_n = zrow;
        if (rr < 7) {
            mch_n = (l < NCHUNK) ? g_mch[l * N_ROWS + row + 1] : FLT_MAX;
            const uint4* rp = reinterpret_cast<const uint4*>(g_dh + (size_t)(row + 1) * 512);
#pragma unroll
            for (int t = 0; t < 4; t++) dq_n[t] = rp[l + 32 * t];
            zrow_n = *reinterpret_cast<const float2*>(z + (size_t)(row + 1) * DIM + 2 * l);
        }

        // row min from chunk mins; per-chunk bias
        float m = mch;
#pragma unroll
        for (int o = 16; o > 0; o >>= 1) m = fminf(m, __shfl_xor_sync(0xFFFFFFFFu, m, o));
        const float bias = (m - mch) * L2E;

        float e[32];
        float Z = 0.f, lemax = 0.f;
#pragma unroll
        for (int t = 0; t < 4; t++) {
            float b = __shfl_sync(0xFFFFFFFFu, bias, (l + 32 * t) >> 3);
            uint32_t us[4] = {dq[t].x, dq[t].y, dq[t].z, dq[t].w};
#pragma unroll
            for (int p = 0; p < 4; p++) {
                __half2 h = *reinterpret_cast<__half2*>(&us[p]);
                float2 dd = __half22float2(h);
                float e0 = ex2f(fmaf(-dd.x, L2E, b));
                float e1 = ex2f(fmaf(-dd.y, L2E, b));
                e[t * 8 + p * 2 + 0] = e0;
                e[t * 8 + p * 2 + 1] = e1;
                Z += e0 + e1;
                lemax = fmaxf(lemax, fmaxf(e0, e1));
            }
        }
        float emax = lemax;
#pragma unroll
        for (int o = 16; o > 0; o >>= 1) {
            Z += __shfl_xor_sync(0xFFFFFFFFu, Z, o);
            emax = fmaxf(emax, __shfl_xor_sync(0xFFFFFFFFu, emax, o));
        }
        const float invZ = __fdividef(1.f, Z);
#pragma unroll
        for (int i = 0; i < 32; i++) soft_acc[i] = fmaf(e[i], invZ, soft_acc[i]);

        // exact refine over all candidates within the window
        const float thr = emax * CANDF;
        float bd = FLT_MAX;
        int bc = 0x7FFFFFFF;
        unsigned bal = __ballot_sync(0xFFFFFFFFu, lemax >= thr);
        while (bal) {
            const int src = __ffs(bal) - 1;
            bal &= bal - 1;
#pragma unroll
            for (int jj = 0; jj < 32; jj++) {
                float ev = __shfl_sync(0xFFFFFFFFu, e[jj], src);
                if (ev >= thr) {
                    const int col = 8 * src + 256 * (jj >> 3) + (jj & 7);
                    float2 cv = *reinterpret_cast<const float2*>(
                        cbk + (size_t)col * DIM + 2 * l);
                    float s = fmaf(cv.x, cv.x, cv.y * cv.y)
                            - 2.f * fmaf(zrow.x, cv.x, zrow.y * cv.y);
#pragma unroll
                    for (int o = 16; o > 0; o >>= 1)
                        s += __shfl_xor_sync(0xFFFFFFFFu, s, o);
                    if (s < bd || (s == bd && col < bc)) { bd = s; bc = col; }
                }
            }
        }

        // fused k3: quantized gather + store + mse
        float2 cv = *reinterpret_cast<const float2*>(cbk + (size_t)bc * DIM + 2 * l);
        *reinterpret_cast<float2*>(out + OFF_Q + (size_t)row * DIM + 2 * l) = cv;
        float dx = cv.x - zrow.x, dy = cv.y - zrow.y;
        sq_acc = fmaf(dx, dx, fmaf(dy, dy, sq_acc));

        if (l == 0) {
            out[OFF_IDX + row] = (float)bc;
            atomicAdd(&g_counts[bc], 1.f);
        }

        mch = mch_n;
#pragma unroll
        for (int t = 0; t < 4; t++) dq[t] = dq_n[t];
        zrow = zrow_n;
    }

    // soft_usage: per-CTA smem accumulation, then global atomics
#pragma unroll
    for (int jj = 0; jj < 32; jj++)
        atomicAdd(&soft_s[8 * l + 256 * (jj >> 3) + (jj & 7)], soft_acc[jj]);

    // mse reduction
#pragma unroll
    for (int o = 16; o > 0; o >>= 1) sq_acc += __shfl_xor_sync(0xFFFFFFFFu, sq_acc, o);
    if (l == 0) ws[w] = sq_acc;
    __syncthreads();
    if (tid == 0) {
        float tt = 0.f;
#pragma unroll
        for (int i = 0; i < 8; i++) tt += ws[i];
        atomicAdd(&g_sq, tt);
    }
    for (int i = tid; i < NCODES; i += 256) atomicAdd(&g_soft[i], soft_s[i]);
}

// ---------------------------------------------------------------------------
// k4: finalize scalars, usage, soft_usage, perplexity.
// ---------------------------------------------------------------------------
__global__ void __launch_bounds__(1024) k4_fin(float* __restrict__ out) {
    const int c = threadIdx.x;
    const float invN = 1.f / (float)N_ROWS;

    float usage = g_counts[c] * invN;
    out[OFF_USAGE + c] = usage;
    out[OFF_SOFT + c]  = g_soft[c] * invN;

    float term = usage * logf(usage + 1e-8f);
#pragma unroll
    for (int o = 16; o > 0; o >>= 1) term += __shfl_xor_sync(0xFFFFFFFFu, term, o);

    __shared__ float red[32];
    if ((c & 31) == 0) red[c >> 5] = term;
    __syncthreads();
    if (c == 0) {
        float sum = 0.f;
#pragma unroll
        for (int i = 0; i < 32; i++) sum += red[i];
        float mse = g_sq / (float)((size_t)N_ROWS * DIM);
        out[OFF_LOSS] = mse * 1.25f;
        out[OFF_CBL]  = mse;
        out[OFF_CML]  = mse;
        out[OFF_PERP] = expf(-sum);
    }
}

// ---------------------------------------------------------------------------
extern "C" void kernel_launch(void* const* d_in, const int* in_sizes, int n_in,
                              void* d_out, int out_size) {
    const float* z   = (const float*)d_in[0];
    const float* cbk = (const float*)d_in[1];
    float* out = (float*)d_out;
    (void)in_sizes; (void)n_in; (void)out_size;

    k0_init<<<4, 256>>>(cbk);
    k1_gemm<<<N_ROWS / MT, 256>>>(z);
    k2_fuse<<<N_ROWS / 64, 256>>>(z, cbk, out);
    k4_fin<<<1, 1024>>>(out);
}

// round 9
// speedup vs baseline: 1.2798x; 1.2798x over previous
#include <cuda_runtime.h>
#include <cuda_bf16.h>
#include <cuda_fp16.h>
#include <math.h>
#include <float.h>
#include <stdint.h>

// ---------------------------------------------------------------------------
// VectorQuantizer: z[32,4096,64] fp32, codebook[1024,64] fp32
// Output (concat float32): quantized[8388608], loss, indices[131072],
//   codebook_loss, commitment_loss, perplexity, usage[1024], soft_usage[1024]
//
// k1: 1-term fp16 m16n8k16 distance GEMM (fp16 in, fp32 accum; error ~6e-3 RMS
//     on d -> soft_usage ~3e-4, argmin resolved exactly in k2).
// k2: softmax/soft_usage from fp16 scratch + exact-fp32 argmin refine.
// ---------------------------------------------------------------------------

#define N_ROWS 131072
#define DIM    64
#define NCODES 1024
#define MT     128
#define BSTR   72
#define NCHUNK 16
#define L2E    1.4426950408889634f
#define CANDF  0.8607080f   /* exp(-0.15): candidate window for fp16 GEMM */

#define OFF_Q     0
#define OFF_LOSS  8388608
#define OFF_IDX   8388609
#define OFF_CBL   8519681
#define OFF_CML   8519682
#define OFF_PERP  8519683
#define OFF_USAGE 8519684
#define OFF_SOFT  8520708

// Scratch (device globals; no allocations allowed).
__device__ uint32_t g_dh[(size_t)N_ROWS * 512];    // 256 MB: fp16x2 of (d - mch)
__device__ float    g_mch[NCHUNK * N_ROWS];        // per-chunk row mins
__device__ uint32_t g_cbh[32 * NCODES];            // fp16x2 packed [k2][n]
__device__ float    g_cc[NCODES];
__device__ int      g_row_idx[N_ROWS];
__device__ float    g_soft[NCODES];
__device__ float    g_counts[NCODES];
__device__ float    g_sq;

// ---------------- helpers ---------------------------------------------------
__device__ __forceinline__ float ex2f(float x) {
    float y;
    asm("ex2.approx.ftz.f32 %0, %1;" : "=f"(y) : "f"(x));
    return y;
}
__device__ __forceinline__ uint32_t smem_u32(const void* p) {
    uint32_t a;
    asm("{ .reg .u64 t; cvta.to.shared.u64 t, %1; cvt.u32.u64 %0, t; }"
        : "=r"(a) : "l"(p));
    return a;
}
__device__ __forceinline__ void cp16(uint32_t dst, const void* src) {
    asm volatile("cp.async.cg.shared.global [%0], [%1], 16;"
                 :: "r"(dst), "l"(src) : "memory");
}
#define CP_COMMIT() asm volatile("cp.async.commit_group;" ::: "memory")
#define CP_WAIT1()  asm volatile("cp.async.wait_group 1;" ::: "memory")

__device__ __forceinline__ uint32_t pk_f16x2(float a, float b) {
    __half2 h = __floats2half2_rn(a, b);
    return *reinterpret_cast<uint32_t*>(&h);
}

#define MMAH(d, a, b0_, b1_) \
    asm volatile("mma.sync.aligned.m16n8k16.row.col.f32.f16.f16.f32 " \
        "{%0,%1,%2,%3}, {%4,%5,%6,%7}, {%8,%9}, {%0,%1,%2,%3};" \
        : "+f"((d)[0]), "+f"((d)[1]), "+f"((d)[2]), "+f"((d)[3]) \
        : "r"((a)[0]), "r"((a)[1]), "r"((a)[2]), "r"((a)[3]), \
          "r"(b0_), "r"(b1_))

// ---------------------------------------------------------------------------
// k0: packed fp16 codebook (transposed [k2][n]) + cc + zero accumulators.
// ---------------------------------------------------------------------------
__global__ void k0_init(const float* __restrict__ cbk) {
    const int c = blockIdx.x * 256 + threadIdx.x;   // 0..1023
    float x[64];
    const float4* p = reinterpret_cast<const float4*>(cbk + (size_t)c * DIM);
    float cs = 0.f;
#pragma unroll
    for (int i = 0; i < 16; i++) {
        float4 v = p[i];
        x[4*i+0] = v.x; x[4*i+1] = v.y; x[4*i+2] = v.z; x[4*i+3] = v.w;
        cs = fmaf(v.x, v.x, fmaf(v.y, v.y, fmaf(v.z, v.z, fmaf(v.w, v.w, cs))));
    }
#pragma unroll
    for (int j = 0; j < 32; j++)
        g_cbh[j * NCODES + c] = pk_f16x2(x[2*j], x[2*j+1]);
    g_cc[c] = cs;
    g_soft[c] = 0.f;
    g_counts[c] = 0.f;
    if (c == 0) g_sq = 0.f;
}

// ---------------------------------------------------------------------------
// k1: 1-term fp16 distance GEMM.  grid = 1024 x 256 thr, 2 CTAs/SM.
//     Warp = 16 rows x 1024 codes (16 chunks of 64).  Outputs fp16 d' + mins.
// ---------------------------------------------------------------------------
__global__ void __launch_bounds__(256, 2) k1_gemm(const float* __restrict__ z) {
    __shared__ uint32_t Bs[2][32 * BSTR];   // [buf][k2*BSTR + n]
    __shared__ float cc_s[NCODES];

    const int tid = threadIdx.x;
    const int w = tid >> 5, l = tid & 31, q = l & 3, nl = l >> 2;
    const int row0 = blockIdx.x * MT;

    // prefetch chunks 0,1 (chunk ch -> buffer ch&1)
#pragma unroll
    for (int p = 0; p < 2; p++) {
#pragma unroll
        for (int i = 0; i < 2; i++) {
            int id = tid + i * 256;
            int k2 = id >> 4, f4 = id & 15;
            cp16(smem_u32(&Bs[p][k2 * BSTR + f4 * 4]),
                 g_cbh + k2 * NCODES + p * 64 + f4 * 4);
        }
        CP_COMMIT();
    }
    *reinterpret_cast<float4*>(&cc_s[tid * 4]) =
        *reinterpret_cast<const float4*>(g_cc + tid * 4);

    // A fragments (fp16) directly from global + per-row zz
    uint32_t Ah[16];
    float zz0 = 0.f, zz1 = 0.f;
    const int r0 = row0 + w * 16 + nl, r1 = r0 + 8;
#pragma unroll
    for (int kc = 0; kc < 4; kc++) {
        const int k = kc * 16 + 2 * q;
        float2 v0 = *reinterpret_cast<const float2*>(z + (size_t)r0 * DIM + k);
        float2 v1 = *reinterpret_cast<const float2*>(z + (size_t)r1 * DIM + k);
        float2 v2 = *reinterpret_cast<const float2*>(z + (size_t)r0 * DIM + k + 8);
        float2 v3 = *reinterpret_cast<const float2*>(z + (size_t)r1 * DIM + k + 8);
        zz0 = fmaf(v0.x, v0.x, fmaf(v0.y, v0.y, fmaf(v2.x, v2.x, fmaf(v2.y, v2.y, zz0))));
        zz1 = fmaf(v1.x, v1.x, fmaf(v1.y, v1.y, fmaf(v3.x, v3.x, fmaf(v3.y, v3.y, zz1))));
        Ah[kc * 4 + 0] = pk_f16x2(v0.x, v0.y);
        Ah[kc * 4 + 1] = pk_f16x2(v1.x, v1.y);
        Ah[kc * 4 + 2] = pk_f16x2(v2.x, v2.y);
        Ah[kc * 4 + 3] = pk_f16x2(v3.x, v3.y);
    }
    zz0 += __shfl_xor_sync(0xFFFFFFFFu, zz0, 1);
    zz0 += __shfl_xor_sync(0xFFFFFFFFu, zz0, 2);
    zz1 += __shfl_xor_sync(0xFFFFFFFFu, zz1, 1);
    zz1 += __shfl_xor_sync(0xFFFFFFFFu, zz1, 2);
    __syncthreads();

#pragma unroll 1
    for (int ch = 0; ch < NCHUNK; ch++) {
        CP_WAIT1();
        __syncthreads();
        const uint32_t* BH = Bs[ch & 1];

        float acc[32];
#pragma unroll
        for (int i = 0; i < 32; i++) acc[i] = 0.f;

#pragma unroll
        for (int kc = 0; kc < 4; kc++) {
            const uint32_t* ah = &Ah[kc * 4];
            const int b0i = (kc * 8 + q) * BSTR + nl;
            const int b1i = (kc * 8 + q + 4) * BSTR + nl;
#pragma unroll
            for (int s = 0; s < 8; s++) {
                uint32_t bh0 = BH[b0i + s * 8];
                uint32_t bh1 = BH[b1i + s * 8];
                MMAH(&acc[s * 4], ah, bh0, bh1);
            }
        }
        __syncthreads();

        if (ch < NCHUNK - 2) {
            const int n0 = (ch + 2) * 64;
#pragma unroll
            for (int i = 0; i < 2; i++) {
                int id = tid + i * 256;
                int k2 = id >> 4, f4 = id & 15;
                cp16(smem_u32(&Bs[ch & 1][k2 * BSTR + f4 * 4]),
                     g_cbh + k2 * NCODES + n0 + f4 * 4);
            }
        }
        CP_COMMIT();

        // epilogue: d = zz + cc - 2*dot; chunk mins; fp16(d - min) store
        float m0 = FLT_MAX, m1 = FLT_MAX;
#pragma unroll
        for (int s = 0; s < 8; s++) {
            float2 cv = *reinterpret_cast<const float2*>(&cc_s[ch * 64 + s * 8 + 2 * q]);
            acc[s*4+0] = fmaf(-2.f, acc[s*4+0], zz0 + cv.x);
            acc[s*4+1] = fmaf(-2.f, acc[s*4+1], zz0 + cv.y);
            acc[s*4+2] = fmaf(-2.f, acc[s*4+2], zz1 + cv.x);
            acc[s*4+3] = fmaf(-2.f, acc[s*4+3], zz1 + cv.y);
            m0 = fminf(m0, fminf(acc[s*4+0], acc[s*4+1]));
            m1 = fminf(m1, fminf(acc[s*4+2], acc[s*4+3]));
        }
        m0 = fminf(m0, __shfl_xor_sync(0xFFFFFFFFu, m0, 1));
        m0 = fminf(m0, __shfl_xor_sync(0xFFFFFFFFu, m0, 2));
        m1 = fminf(m1, __shfl_xor_sync(0xFFFFFFFFu, m1, 1));
        m1 = fminf(m1, __shfl_xor_sync(0xFFFFFFFFu, m1, 2));
        if (q == 0) {
            g_mch[ch * N_ROWS + r0] = m0;
            g_mch[ch * N_ROWS + r1] = m1;
        }
        uint32_t* o0 = g_dh + (size_t)r0 * 512 + ch * 32 + q;
        uint32_t* o1 = g_dh + (size_t)r1 * 512 + ch * 32 + q;
#pragma unroll
        for (int s = 0; s < 8; s++) {
            o0[s * 4] = pk_f16x2(acc[s*4+0] - m0, acc[s*4+1] - m0);
            o1[s * 4] = pk_f16x2(acc[s*4+2] - m1, acc[s*4+3] - m1);
        }
    }
}

// ---------------------------------------------------------------------------
// k2: Z + soft_usage + exact argmin refine + counts + index output.
//     warp-per-row (16 rows/warp), grid = 1024 x 256.
// ---------------------------------------------------------------------------
__global__ void __launch_bounds__(256) k2_fuse(const float* __restrict__ z,
                                               const float* __restrict__ cbk,
                                               float* __restrict__ out) {
    __shared__ float soft_s[NCODES];
    const int tid = threadIdx.x, w = tid >> 5, l = tid & 31;
    for (int i = tid; i < NCODES; i += 256) soft_s[i] = 0.f;
    __syncthreads();

    float soft_acc[32];
#pragma unroll
    for (int i = 0; i < 32; i++) soft_acc[i] = 0.f;

    const int rbase = blockIdx.x * 128 + w * 16;
#pragma unroll 1
    for (int rr = 0; rr < 16; rr++) {
        const int row = rbase + rr;
        // row min from chunk mins; per-chunk bias
        float mch = (l < NCHUNK) ? g_mch[l * N_ROWS + row] : FLT_MAX;
        float m = mch;
#pragma unroll
        for (int o = 16; o > 0; o >>= 1) m = fminf(m, __shfl_xor_sync(0xFFFFFFFFu, m, o));
        const float bias = (m - mch) * L2E;

        const uint4* rp = reinterpret_cast<const uint4*>(g_dh + (size_t)row * 512);
        const float2 zrow = *reinterpret_cast<const float2*>(z + (size_t)row * DIM + 2 * l);

        float e[32];
        float Z = 0.f, lemax = 0.f;
#pragma unroll
        for (int t = 0; t < 4; t++) {
            uint4 uq = rp[l + 32 * t];
            float b = __shfl_sync(0xFFFFFFFFu, bias, (l + 32 * t) >> 3);
            uint32_t us[4] = {uq.x, uq.y, uq.z, uq.w};
#pragma unroll
            for (int p = 0; p < 4; p++) {
                __half2 h = *reinterpret_cast<__half2*>(&us[p]);
                float2 dd = __half22float2(h);
                float e0 = ex2f(fmaf(-dd.x, L2E, b));
                float e1 = ex2f(fmaf(-dd.y, L2E, b));
                e[t * 8 + p * 2 + 0] = e0;
                e[t * 8 + p * 2 + 1] = e1;
                Z += e0 + e1;
                lemax = fmaxf(lemax, fmaxf(e0, e1));
            }
        }
        float emax = lemax;
#pragma unroll
        for (int o = 16; o > 0; o >>= 1) {
            Z += __shfl_xor_sync(0xFFFFFFFFu, Z, o);
            emax = fmaxf(emax, __shfl_xor_sync(0xFFFFFFFFu, emax, o));
        }
        const float invZ = __fdividef(1.f, Z);
#pragma unroll
        for (int i = 0; i < 32; i++) soft_acc[i] = fmaf(e[i], invZ, soft_acc[i]);

        // exact refine over all candidates within the window
        const float thr = emax * CANDF;
        float bd = FLT_MAX;
        int bc = 0x7FFFFFFF;
        unsigned bal = __ballot_sync(0xFFFFFFFFu, lemax >= thr);
        while (bal) {
            const int src = __ffs(bal) - 1;
            bal &= bal - 1;
#pragma unroll
            for (int jj = 0; jj < 32; jj++) {
                float ev = __shfl_sync(0xFFFFFFFFu, e[jj], src);
                if (ev >= thr) {
                    const int col = 8 * src + 256 * (jj >> 3) + (jj & 7);
                    float2 cv = *reinterpret_cast<const float2*>(
                        cbk + (size_t)col * DIM + 2 * l);
                    float s = fmaf(cv.x, cv.x, cv.y * cv.y)
                            - 2.f * fmaf(zrow.x, cv.x, zrow.y * cv.y);
#pragma unroll
                    for (int o = 16; o > 0; o >>= 1)
                        s += __shfl_xor_sync(0xFFFFFFFFu, s, o);
                    if (s < bd || (s == bd && col < bc)) { bd = s; bc = col; }
                }
            }
        }
        if (l == 0) {
            g_row_idx[row] = bc;
            out[OFF_IDX + row] = (float)bc;
            atomicAdd(&g_counts[bc], 1.f);
        }
    }
#pragma unroll
    for (int jj = 0; jj < 32; jj++)
        atomicAdd(&soft_s[8 * l + 256 * (jj >> 3) + (jj & 7)], soft_acc[jj]);
    __syncthreads();
    for (int i = tid; i < NCODES; i += 256) atomicAdd(&g_soft[i], soft_s[i]);
}

// ---------------------------------------------------------------------------
// k3: gather quantized + mse.  One thread per float4.
// ---------------------------------------------------------------------------
__global__ void __launch_bounds__(256) k3_quant(const float* __restrict__ z,
                                                const float* __restrict__ cbk,
                                                float* __restrict__ out) {
    const int t = blockIdx.x * 256 + threadIdx.x;
    const int row = t >> 4, q = t & 15;
    const int idx = g_row_idx[row];
    float4 c = *reinterpret_cast<const float4*>(cbk + (size_t)idx * DIM + q * 4);
    float4 zv = *reinterpret_cast<const float4*>(z + (size_t)t * 4);
    *reinterpret_cast<float4*>(out + OFF_Q + (size_t)t * 4) = c;

    float dx = c.x - zv.x, dy = c.y - zv.y, dz = c.z - zv.z, dw = c.w - zv.w;
    float s = dx*dx + dy*dy + dz*dz + dw*dw;
#pragma unroll
    for (int o = 16; o > 0; o >>= 1) s += __shfl_xor_sync(0xFFFFFFFFu, s, o);

    __shared__ float ws[8];
    if ((threadIdx.x & 31) == 0) ws[threadIdx.x >> 5] = s;
    __syncthreads();
    if (threadIdx.x == 0) {
        float tt = 0.f;
#pragma unroll
        for (int i = 0; i < 8; i++) tt += ws[i];
        atomicAdd(&g_sq, tt);
    }
}

// ---------------------------------------------------------------------------
// k4: finalize scalars, usage, soft_usage, perplexity.
// ---------------------------------------------------------------------------
__global__ void __launch_bounds__(1024) k4_fin(float* __restrict__ out) {
    const int c = threadIdx.x;
    const float invN = 1.f / (float)N_ROWS;

    float usage = g_counts[c] * invN;
    out[OFF_USAGE + c] = usage;
    out[OFF_SOFT + c]  = g_soft[c] * invN;

    float term = usage * logf(usage + 1e-8f);
#pragma unroll
    for (int o = 16; o > 0; o >>= 1) term += __shfl_xor_sync(0xFFFFFFFFu, term, o);

    __shared__ float red[32];
    if ((c & 31) == 0) red[c >> 5] = term;
    __syncthreads();
    if (c == 0) {
        float sum = 0.f;
#pragma unroll
        for (int i = 0; i < 32; i++) sum += red[i];
        float mse = g_sq / (float)((size_t)N_ROWS * DIM);
        out[OFF_LOSS] = mse * 1.25f;
        out[OFF_CBL]  = mse;
        out[OFF_CML]  = mse;
        out[OFF_PERP] = expf(-sum);
    }
}

// ---------------------------------------------------------------------------
extern "C" void kernel_launch(void* const* d_in, const int* in_sizes, int n_in,
                              void* d_out, int out_size) {
    const float* z   = (const float*)d_in[0];
    const float* cbk = (const float*)d_in[1];
    float* out = (float*)d_out;
    (void)in_sizes; (void)n_in; (void)out_size;

    k0_init<<<4, 256>>>(cbk);
    k1_gemm<<<N_ROWS / MT, 256>>>(z);
    k2_fuse<<<N_ROWS / 128, 256>>>(z, cbk, out);
    k3_quant<<<(N_ROWS * DIM / 4) / 256, 256>>>(z, cbk, out);
    k4_fin<<<1, 1024>>>(out);
}

// round 10
// speedup vs baseline: 1.3501x; 1.0549x over previous
#include <cuda_runtime.h>
#include <cuda_bf16.h>
#include <cuda_fp16.h>
#include <math.h>
#include <float.h>
#include <stdint.h>

// ---------------------------------------------------------------------------
// VectorQuantizer: z[32,4096,64] fp32, codebook[1024,64] fp32
// Output (concat float32): quantized[8388608], loss, indices[131072],
//   codebook_loss, commitment_loss, perplexity, usage[1024], soft_usage[1024]
//
// k1: 1-term fp16 m16n8k16 distance GEMM, 3-stage cp.async ring (1 sync/chunk),
//     stores fp16(d - chunk_min) + chunk mins.
// k2: softmax/soft_usage from fp16 scratch + exact-fp32 argmin refine +
//     fused quantized gather/store + mse (k3 folded in).
// ---------------------------------------------------------------------------

#define N_ROWS 131072
#define DIM    64
#define NCODES 1024
#define MT     128
#define BSTR   72
#define NCHUNK 16
#define L2E    1.4426950408889634f
#define CANDF  0.8607080f   /* exp(-0.15): candidate window for fp16 GEMM */

#define OFF_Q     0
#define OFF_LOSS  8388608
#define OFF_IDX   8388609
#define OFF_CBL   8519681
#define OFF_CML   8519682
#define OFF_PERP  8519683
#define OFF_USAGE 8519684
#define OFF_SOFT  8520708

// Scratch (device globals; no allocations allowed).
__device__ uint32_t g_dh[(size_t)N_ROWS * 512];    // 256 MB: fp16x2 of (d - mch)
__device__ float    g_mch[NCHUNK * N_ROWS];        // per-chunk row mins
__device__ uint32_t g_cbh[32 * NCODES];            // fp16x2 packed [k2][n]
__device__ float    g_cc[NCODES];
__device__ float    g_soft[NCODES];
__device__ float    g_counts[NCODES];
__device__ float    g_sq;

// ---------------- helpers ---------------------------------------------------
__device__ __forceinline__ float ex2f(float x) {
    float y;
    asm("ex2.approx.ftz.f32 %0, %1;" : "=f"(y) : "f"(x));
    return y;
}
__device__ __forceinline__ uint32_t smem_u32(const void* p) {
    uint32_t a;
    asm("{ .reg .u64 t; cvta.to.shared.u64 t, %1; cvt.u32.u64 %0, t; }"
        : "=r"(a) : "l"(p));
    return a;
}
__device__ __forceinline__ void cp16(uint32_t dst, const void* src) {
    asm volatile("cp.async.cg.shared.global [%0], [%1], 16;"
                 :: "r"(dst), "l"(src) : "memory");
}
#define CP_COMMIT() asm volatile("cp.async.commit_group;" ::: "memory")
#define CP_WAIT1()  asm volatile("cp.async.wait_group 1;" ::: "memory")

__device__ __forceinline__ uint32_t pk_f16x2(float a, float b) {
    __half2 h = __floats2half2_rn(a, b);
    return *reinterpret_cast<uint32_t*>(&h);
}

#define MMAH(d, a, b0_, b1_) \
    asm volatile("mma.sync.aligned.m16n8k16.row.col.f32.f16.f16.f32 " \
        "{%0,%1,%2,%3}, {%4,%5,%6,%7}, {%8,%9}, {%0,%1,%2,%3};" \
        : "+f"((d)[0]), "+f"((d)[1]), "+f"((d)[2]), "+f"((d)[3]) \
        : "r"((a)[0]), "r"((a)[1]), "r"((a)[2]), "r"((a)[3]), \
          "r"(b0_), "r"(b1_))

// ---------------------------------------------------------------------------
// k0: packed fp16 codebook (transposed [k2][n]) + cc + zero accumulators.
// ---------------------------------------------------------------------------
__global__ void k0_init(const float* __restrict__ cbk) {
    const int c = blockIdx.x * 256 + threadIdx.x;   // 0..1023
    float x[64];
    const float4* p = reinterpret_cast<const float4*>(cbk + (size_t)c * DIM);
    float cs = 0.f;
#pragma unroll
    for (int i = 0; i < 16; i++) {
        float4 v = p[i];
        x[4*i+0] = v.x; x[4*i+1] = v.y; x[4*i+2] = v.z; x[4*i+3] = v.w;
        cs = fmaf(v.x, v.x, fmaf(v.y, v.y, fmaf(v.z, v.z, fmaf(v.w, v.w, cs))));
    }
#pragma unroll
    for (int j = 0; j < 32; j++)
        g_cbh[j * NCODES + c] = pk_f16x2(x[2*j], x[2*j+1]);
    g_cc[c] = cs;
    g_soft[c] = 0.f;
    g_counts[c] = 0.f;
    if (c == 0) g_sq = 0.f;
}

// ---------------------------------------------------------------------------
// k1: 1-term fp16 distance GEMM.  grid = 1024 x 256 thr, 2 CTAs/SM.
//     3-stage cp.async ring: ONE __syncthreads per chunk.
//     Warp = 16 rows x 1024 codes (16 chunks of 64).  Outputs fp16 d' + mins.
// ---------------------------------------------------------------------------
__global__ void __launch_bounds__(256, 2) k1_gemm(const float* __restrict__ z) {
    __shared__ uint32_t Bs[3][32 * BSTR];   // [ring buf][k2*BSTR + n]
    __shared__ float cc_s[NCODES];

    const int tid = threadIdx.x;
    const int w = tid >> 5, l = tid & 31, q = l & 3, nl = l >> 2;
    const int row0 = blockIdx.x * MT;

    // prefetch chunk 0 -> Bs[0], chunk 1 -> Bs[1]
#pragma unroll
    for (int p = 0; p < 2; p++) {
#pragma unroll
        for (int i = 0; i < 2; i++) {
            int id = tid + i * 256;
            int k2 = id >> 4, f4 = id & 15;
            cp16(smem_u32(&Bs[p][k2 * BSTR + f4 * 4]),
                 g_cbh + k2 * NCODES + p * 64 + f4 * 4);
        }
        CP_COMMIT();
    }
    *reinterpret_cast<float4*>(&cc_s[tid * 4]) =
        *reinterpret_cast<const float4*>(g_cc + tid * 4);

    // A fragments (fp16) directly from global + per-row zz
    uint32_t Ah[16];
    float zz0 = 0.f, zz1 = 0.f;
    const int r0 = row0 + w * 16 + nl, r1 = r0 + 8;
#pragma unroll
    for (int kc = 0; kc < 4; kc++) {
        const int k = kc * 16 + 2 * q;
        float2 v0 = *reinterpret_cast<const float2*>(z + (size_t)r0 * DIM + k);
        float2 v1 = *reinterpret_cast<const float2*>(z + (size_t)r1 * DIM + k);
        float2 v2 = *reinterpret_cast<const float2*>(z + (size_t)r0 * DIM + k + 8);
        float2 v3 = *reinterpret_cast<const float2*>(z + (size_t)r1 * DIM + k + 8);
        zz0 = fmaf(v0.x, v0.x, fmaf(v0.y, v0.y, fmaf(v2.x, v2.x, fmaf(v2.y, v2.y, zz0))));
        zz1 = fmaf(v1.x, v1.x, fmaf(v1.y, v1.y, fmaf(v3.x, v3.x, fmaf(v3.y, v3.y, zz1))));
        Ah[kc * 4 + 0] = pk_f16x2(v0.x, v0.y);
        Ah[kc * 4 + 1] = pk_f16x2(v1.x, v1.y);
        Ah[kc * 4 + 2] = pk_f16x2(v2.x, v2.y);
        Ah[kc * 4 + 3] = pk_f16x2(v3.x, v3.y);
    }
    zz0 += __shfl_xor_sync(0xFFFFFFFFu, zz0, 1);
    zz0 += __shfl_xor_sync(0xFFFFFFFFu, zz0, 2);
    zz1 += __shfl_xor_sync(0xFFFFFFFFu, zz1, 1);
    zz1 += __shfl_xor_sync(0xFFFFFFFFu, zz1, 2);

#pragma unroll 1
    for (int ch = 0; ch < NCHUNK; ch++) {
        CP_WAIT1();
        __syncthreads();   // buf ch%3 ready AND all warps done reading buf (ch-1)%3

        // prefetch chunk ch+2 into buf (ch+2)%3 == (ch-1)%3 (safe: see sync above)
        if (ch < NCHUNK - 2) {
            const int n0 = (ch + 2) * 64;
            const int pb = (ch + 2) % 3;
#pragma unroll
            for (int i = 0; i < 2; i++) {
                int id = tid + i * 256;
                int k2 = id >> 4, f4 = id & 15;
                cp16(smem_u32(&Bs[pb][k2 * BSTR + f4 * 4]),
                     g_cbh + k2 * NCODES + n0 + f4 * 4);
            }
        }
        CP_COMMIT();

        const uint32_t* BH = Bs[ch % 3];

        float acc[32];
#pragma unroll
        for (int i = 0; i < 32; i++) acc[i] = 0.f;

#pragma unroll
        for (int kc = 0; kc < 4; kc++) {
            const uint32_t* ah = &Ah[kc * 4];
            const int b0i = (kc * 8 + q) * BSTR + nl;
            const int b1i = (kc * 8 + q + 4) * BSTR + nl;
#pragma unroll
            for (int s = 0; s < 8; s++) {
                uint32_t bh0 = BH[b0i + s * 8];
                uint32_t bh1 = BH[b1i + s * 8];
                MMAH(&acc[s * 4], ah, bh0, bh1);
            }
        }

        // epilogue: d = zz + cc - 2*dot; chunk mins; fp16(d - min) store
        float m0 = FLT_MAX, m1 = FLT_MAX;
#pragma unroll
        for (int s = 0; s < 8; s++) {
            float2 cv = *reinterpret_cast<const float2*>(&cc_s[ch * 64 + s * 8 + 2 * q]);
            acc[s*4+0] = fmaf(-2.f, acc[s*4+0], zz0 + cv.x);
            acc[s*4+1] = fmaf(-2.f, acc[s*4+1], zz0 + cv.y);
            acc[s*4+2] = fmaf(-2.f, acc[s*4+2], zz1 + cv.x);
            acc[s*4+3] = fmaf(-2.f, acc[s*4+3], zz1 + cv.y);
            m0 = fminf(m0, fminf(acc[s*4+0], acc[s*4+1]));
            m1 = fminf(m1, fminf(acc[s*4+2], acc[s*4+3]));
        }
        m0 = fminf(m0, __shfl_xor_sync(0xFFFFFFFFu, m0, 1));
        m0 = fminf(m0, __shfl_xor_sync(0xFFFFFFFFu, m0, 2));
        m1 = fminf(m1, __shfl_xor_sync(0xFFFFFFFFu, m1, 1));
        m1 = fminf(m1, __shfl_xor_sync(0xFFFFFFFFu, m1, 2));
        if (q == 0) {
            g_mch[ch * N_ROWS + r0] = m0;
            g_mch[ch * N_ROWS + r1] = m1;
        }
        uint32_t* o0 = g_dh + (size_t)r0 * 512 + ch * 32 + q;
        uint32_t* o1 = g_dh + (size_t)r1 * 512 + ch * 32 + q;
#pragma unroll
        for (int s = 0; s < 8; s++) {
            o0[s * 4] = pk_f16x2(acc[s*4+0] - m0, acc[s*4+1] - m0);
            o1[s * 4] = pk_f16x2(acc[s*4+2] - m1, acc[s*4+3] - m1);
        }
    }
}

// ---------------------------------------------------------------------------
// k2: Z + soft_usage + exact argmin refine + counts + indices + quantized
//     gather/store + mse (k3 fused).  warp-per-row (16 rows/warp), grid 1024.
// ---------------------------------------------------------------------------
__global__ void __launch_bounds__(256) k2_fuse(const float* __restrict__ z,
                                               const float* __restrict__ cbk,
                                               float* __restrict__ out) {
    __shared__ float soft_s[NCODES];
    __shared__ float ws[8];
    const int tid = threadIdx.x, w = tid >> 5, l = tid & 31;
    for (int i = tid; i < NCODES; i += 256) soft_s[i] = 0.f;
    __syncthreads();

    float soft_acc[32];
#pragma unroll
    for (int i = 0; i < 32; i++) soft_acc[i] = 0.f;
    float sq_acc = 0.f;

    const int rbase = blockIdx.x * 128 + w * 16;
#pragma unroll 1
    for (int rr = 0; rr < 16; rr++) {
        const int row = rbase + rr;
        // row min from chunk mins; per-chunk bias
        float mch = (l < NCHUNK) ? g_mch[l * N_ROWS + row] : FLT_MAX;
        float m = mch;
#pragma unroll
        for (int o = 16; o > 0; o >>= 1) m = fminf(m, __shfl_xor_sync(0xFFFFFFFFu, m, o));
        const float bias = (m - mch) * L2E;

        const uint4* rp = reinterpret_cast<const uint4*>(g_dh + (size_t)row * 512);
        const float2 zrow = *reinterpret_cast<const float2*>(z + (size_t)row * DIM + 2 * l);

        float e[32];
        float Z = 0.f, lemax = 0.f;
#pragma unroll
        for (int t = 0; t < 4; t++) {
            uint4 uq = rp[l + 32 * t];
            float b = __shfl_sync(0xFFFFFFFFu, bias, (l + 32 * t) >> 3);
            uint32_t us[4] = {uq.x, uq.y, uq.z, uq.w};
#pragma unroll
            for (int p = 0; p < 4; p++) {
                __half2 h = *reinterpret_cast<__half2*>(&us[p]);
                float2 dd = __half22float2(h);
                float e0 = ex2f(fmaf(-dd.x, L2E, b));
                float e1 = ex2f(fmaf(-dd.y, L2E, b));
                e[t * 8 + p * 2 + 0] = e0;
                e[t * 8 + p * 2 + 1] = e1;
                Z += e0 + e1;
                lemax = fmaxf(lemax, fmaxf(e0, e1));
            }
        }
        float emax = lemax;
#pragma unroll
        for (int o = 16; o > 0; o >>= 1) {
            Z += __shfl_xor_sync(0xFFFFFFFFu, Z, o);
            emax = fmaxf(emax, __shfl_xor_sync(0xFFFFFFFFu, emax, o));
        }
        const float invZ = __fdividef(1.f, Z);
#pragma unroll
        for (int i = 0; i < 32; i++) soft_acc[i] = fmaf(e[i], invZ, soft_acc[i]);

        // exact refine over all candidates within the window
        const float thr = emax * CANDF;
        float bd = FLT_MAX;
        int bc = 0x7FFFFFFF;
        unsigned bal = __ballot_sync(0xFFFFFFFFu, lemax >= thr);
        while (bal) {
            const int src = __ffs(bal) - 1;
            bal &= bal - 1;
#pragma unroll
            for (int jj = 0; jj < 32; jj++) {
                float ev = __shfl_sync(0xFFFFFFFFu, e[jj], src);
                if (ev >= thr) {
                    const int col = 8 * src + 256 * (jj >> 3) + (jj & 7);
                    float2 cv = *reinterpret_cast<const float2*>(
                        cbk + (size_t)col * DIM + 2 * l);
                    float s = fmaf(cv.x, cv.x, cv.y * cv.y)
                            - 2.f * fmaf(zrow.x, cv.x, zrow.y * cv.y);
#pragma unroll
                    for (int o = 16; o > 0; o >>= 1)
                        s += __shfl_xor_sync(0xFFFFFFFFu, s, o);
                    if (s < bd || (s == bd && col < bc)) { bd = s; bc = col; }
                }
            }
        }

        // fused k3: quantized gather + store + mse
        float2 cq = *reinterpret_cast<const float2*>(cbk + (size_t)bc * DIM + 2 * l);
        *reinterpret_cast<float2*>(out + OFF_Q + (size_t)row * DIM + 2 * l) = cq;
        float dx = cq.x - zrow.x, dy = cq.y - zrow.y;
        sq_acc = fmaf(dx, dx, fmaf(dy, dy, sq_acc));

        if (l == 0) {
            out[OFF_IDX + row] = (float)bc;
            atomicAdd(&g_counts[bc], 1.f);
        }
    }
#pragma unroll
    for (int jj = 0; jj < 32; jj++)
        atomicAdd(&soft_s[8 * l + 256 * (jj >> 3) + (jj & 7)], soft_acc[jj]);

#pragma unroll
    for (int o = 16; o > 0; o >>= 1) sq_acc += __shfl_xor_sync(0xFFFFFFFFu, sq_acc, o);
    if (l == 0) ws[w] = sq_acc;
    __syncthreads();
    if (tid == 0) {
        float tt = 0.f;
#pragma unroll
        for (int i = 0; i < 8; i++) tt += ws[i];
        atomicAdd(&g_sq, tt);
    }
    for (int i = tid; i < NCODES; i += 256) atomicAdd(&g_soft[i], soft_s[i]);
}

// ---------------------------------------------------------------------------
// k4: finalize scalars, usage, soft_usage, perplexity.
// ---------------------------------------------------------------------------
__global__ void __launch_bounds__(1024) k4_fin(float* __restrict__ out) {
    const int c = threadIdx.x;
    const float invN = 1.f / (float)N_ROWS;

    float usage = g_counts[c] * invN;
    out[OFF_USAGE + c] = usage;
    out[OFF_SOFT + c]  = g_soft[c] * invN;

    float term = usage * logf(usage + 1e-8f);
#pragma unroll
    for (int o = 16; o > 0; o >>= 1) term += __shfl_xor_sync(0xFFFFFFFFu, term, o);

    __shared__ float red[32];
    if ((c & 31) == 0) red[c >> 5] = term;
    __syncthreads();
    if (c == 0) {
        float sum = 0.f;
#pragma unroll
        for (int i = 0; i < 32; i++) sum += red[i];
        float mse = g_sq / (float)((size_t)N_ROWS * DIM);
        out[OFF_LOSS] = mse * 1.25f;
        out[OFF_CBL]  = mse;
        out[OFF_CML]  = mse;
        out[OFF_PERP] = expf(-sum);
    }
}

// ---------------------------------------------------------------------------
extern "C" void kernel_launch(void* const* d_in, const int* in_sizes, int n_in,
                              void* d_out, int out_size) {
    const float* z   = (const float*)d_in[0];
    const float* cbk = (const float*)d_in[1];
    float* out = (float*)d_out;
    (void)in_sizes; (void)n_in; (void)out_size;

    k0_init<<<4, 256>>>(cbk);
    k1_gemm<<<N_ROWS / MT, 256>>>(z);
    k2_fuse<<<N_ROWS / 128, 256>>>(z, cbk, out);
    k4_fin<<<1, 1024>>>(out);
}

// round 11
// speedup vs baseline: 1.3764x; 1.0195x over previous
#include <cuda_runtime.h>
#include <cuda_bf16.h>
#include <cuda_fp16.h>
#include <math.h>
#include <float.h>
#include <stdint.h>

// ---------------------------------------------------------------------------
// VectorQuantizer: z[32,4096,64] fp32, codebook[1024,64] fp32
// Output (concat float32): quantized[8388608], loss, indices[131072],
//   codebook_loss, commitment_loss, perplexity, usage[1024], soft_usage[1024]
//
// k1: 1-term fp16 m16n8k16 distance GEMM, 3-stage cp.async ring,
//     COALESCED scratch stores via warp-private smem staging.
// k2: softmax/soft_usage from fp16 scratch (half2 ex2 -> MUFU halved) +
//     exact-fp32 argmin refine + fused quantized gather/store + mse.
// ---------------------------------------------------------------------------

#define N_ROWS 131072
#define DIM    64
#define NCODES 1024
#define MT     128
#define BSTR   72
#define NCHUNK 16
#define L2E    1.4426950408889634f
#define CANDF  0.8607080f   /* exp(-0.15): candidate window for fp16 GEMM */

#define OFF_Q     0
#define OFF_LOSS  8388608
#define OFF_IDX   8388609
#define OFF_CBL   8519681
#define OFF_CML   8519682
#define OFF_PERP  8519683
#define OFF_USAGE 8519684
#define OFF_SOFT  8520708

// Scratch (device globals; no allocations allowed).
__device__ uint32_t g_dh[(size_t)N_ROWS * 512];    // 256 MB: fp16x2 of (d - mch)
__device__ float    g_mch[(size_t)N_ROWS * NCHUNK]; // per-row per-chunk mins [row][ch]
__device__ uint32_t g_cbh[32 * NCODES];            // fp16x2 packed [k2][n]
__device__ float    g_cc[NCODES];
__device__ float    g_soft[NCODES];
__device__ float    g_counts[NCODES];
__device__ float    g_sq;

// ---------------- helpers ---------------------------------------------------
__device__ __forceinline__ uint32_t smem_u32(const void* p) {
    uint32_t a;
    asm("{ .reg .u64 t; cvta.to.shared.u64 t, %1; cvt.u32.u64 %0, t; }"
        : "=r"(a) : "l"(p));
    return a;
}
__device__ __forceinline__ void cp16(uint32_t dst, const void* src) {
    asm volatile("cp.async.cg.shared.global [%0], [%1], 16;"
                 :: "r"(dst), "l"(src) : "memory");
}
#define CP_COMMIT() asm volatile("cp.async.commit_group;" ::: "memory")
#define CP_WAIT1()  asm volatile("cp.async.wait_group 1;" ::: "memory")

__device__ __forceinline__ uint32_t pk_f16x2(float a, float b) {
    __half2 h = __floats2half2_rn(a, b);
    return *reinterpret_cast<uint32_t*>(&h);
}

#define MMAH(d, a, b0_, b1_) \
    asm volatile("mma.sync.aligned.m16n8k16.row.col.f32.f16.f16.f32 " \
        "{%0,%1,%2,%3}, {%4,%5,%6,%7}, {%8,%9}, {%0,%1,%2,%3};" \
        : "+f"((d)[0]), "+f"((d)[1]), "+f"((d)[2]), "+f"((d)[3]) \
        : "r"((a)[0]), "r"((a)[1]), "r"((a)[2]), "r"((a)[3]), \
          "r"(b0_), "r"(b1_))

// ---------------------------------------------------------------------------
// k0: packed fp16 codebook (transposed [k2][n]) + cc + zero accumulators.
// ---------------------------------------------------------------------------
__global__ void k0_init(const float* __restrict__ cbk) {
    const int c = blockIdx.x * 256 + threadIdx.x;   // 0..1023
    float x[64];
    const float4* p = reinterpret_cast<const float4*>(cbk + (size_t)c * DIM);
    float cs = 0.f;
#pragma unroll
    for (int i = 0; i < 16; i++) {
        float4 v = p[i];
        x[4*i+0] = v.x; x[4*i+1] = v.y; x[4*i+2] = v.z; x[4*i+3] = v.w;
        cs = fmaf(v.x, v.x, fmaf(v.y, v.y, fmaf(v.z, v.z, fmaf(v.w, v.w, cs))));
    }
#pragma unroll
    for (int j = 0; j < 32; j++)
        g_cbh[j * NCODES + c] = pk_f16x2(x[2*j], x[2*j+1]);
    g_cc[c] = cs;
    g_soft[c] = 0.f;
    g_counts[c] = 0.f;
    if (c == 0) g_sq = 0.f;
}

// ---------------------------------------------------------------------------
// k1: 1-term fp16 distance GEMM.  grid = 1024 x 256 thr, 2 CTAs/SM.
//     3-stage cp.async ring, ONE __syncthreads per chunk.
//     Scratch stores staged through warp-private smem -> STG.128 coalesced.
// ---------------------------------------------------------------------------
__global__ void __launch_bounds__(256, 2) k1_gemm(const float* __restrict__ z) {
    __shared__ uint32_t Bs[3][32 * BSTR];            // B ring
    __shared__ float cc_s[NCODES];
    __shared__ __align__(16) uint32_t stg[8][288];   // warp-private staging (36/row)

    const int tid = threadIdx.x;
    const int w = tid >> 5, l = tid & 31, q = l & 3, nl = l >> 2;
    const int row0 = blockIdx.x * MT;

    // prefetch chunk 0 -> Bs[0], chunk 1 -> Bs[1]
#pragma unroll
    for (int p = 0; p < 2; p++) {
#pragma unroll
        for (int i = 0; i < 2; i++) {
            int id = tid + i * 256;
            int k2 = id >> 4, f4 = id & 15;
            cp16(smem_u32(&Bs[p][k2 * BSTR + f4 * 4]),
                 g_cbh + k2 * NCODES + p * 64 + f4 * 4);
        }
        CP_COMMIT();
    }
    *reinterpret_cast<float4*>(&cc_s[tid * 4]) =
        *reinterpret_cast<const float4*>(g_cc + tid * 4);

    // A fragments (fp16) directly from global + per-row zz
    uint32_t Ah[16];
    float zz0 = 0.f, zz1 = 0.f;
    const int r0 = row0 + w * 16 + nl, r1 = r0 + 8;
#pragma unroll
    for (int kc = 0; kc < 4; kc++) {
        const int k = kc * 16 + 2 * q;
        float2 v0 = *reinterpret_cast<const float2*>(z + (size_t)r0 * DIM + k);
        float2 v1 = *reinterpret_cast<const float2*>(z + (size_t)r1 * DIM + k);
        float2 v2 = *reinterpret_cast<const float2*>(z + (size_t)r0 * DIM + k + 8);
        float2 v3 = *reinterpret_cast<const float2*>(z + (size_t)r1 * DIM + k + 8);
        zz0 = fmaf(v0.x, v0.x, fmaf(v0.y, v0.y, fmaf(v2.x, v2.x, fmaf(v2.y, v2.y, zz0))));
        zz1 = fmaf(v1.x, v1.x, fmaf(v1.y, v1.y, fmaf(v3.x, v3.x, fmaf(v3.y, v3.y, zz1))));
        Ah[kc * 4 + 0] = pk_f16x2(v0.x, v0.y);
        Ah[kc * 4 + 1] = pk_f16x2(v1.x, v1.y);
        Ah[kc * 4 + 2] = pk_f16x2(v2.x, v2.y);
        Ah[kc * 4 + 3] = pk_f16x2(v3.x, v3.y);
    }
    zz0 += __shfl_xor_sync(0xFFFFFFFFu, zz0, 1);
    zz0 += __shfl_xor_sync(0xFFFFFFFFu, zz0, 2);
    zz1 += __shfl_xor_sync(0xFFFFFFFFu, zz1, 1);
    zz1 += __shfl_xor_sync(0xFFFFFFFFu, zz1, 2);

#pragma unroll 1
    for (int ch = 0; ch < NCHUNK; ch++) {
        CP_WAIT1();
        __syncthreads();   // buf ch%3 ready AND all warps done reading buf (ch-1)%3

        // prefetch chunk ch+2 into buf (ch+2)%3 == (ch-1)%3 (safe: see sync above)
        if (ch < NCHUNK - 2) {
            const int n0 = (ch + 2) * 64;
            const int pb = (ch + 2) % 3;
#pragma unroll
            for (int i = 0; i < 2; i++) {
                int id = tid + i * 256;
                int k2 = id >> 4, f4 = id & 15;
                cp16(smem_u32(&Bs[pb][k2 * BSTR + f4 * 4]),
                     g_cbh + k2 * NCODES + n0 + f4 * 4);
            }
        }
        CP_COMMIT();

        const uint32_t* BH = Bs[ch % 3];

        float acc[32];
#pragma unroll
        for (int i = 0; i < 32; i++) acc[i] = 0.f;

#pragma unroll
        for (int kc = 0; kc < 4; kc++) {
            const uint32_t* ah = &Ah[kc * 4];
            const int b0i = (kc * 8 + q) * BSTR + nl;
            const int b1i = (kc * 8 + q + 4) * BSTR + nl;
#pragma unroll
            for (int s = 0; s < 8; s++) {
                uint32_t bh0 = BH[b0i + s * 8];
                uint32_t bh1 = BH[b1i + s * 8];
                MMAH(&acc[s * 4], ah, bh0, bh1);
            }
        }

        // epilogue: d = zz + cc - 2*dot; chunk mins
        float m0 = FLT_MAX, m1 = FLT_MAX;
#pragma unroll
        for (int s = 0; s < 8; s++) {
            float2 cv = *reinterpret_cast<const float2*>(&cc_s[ch * 64 + s * 8 + 2 * q]);
            acc[s*4+0] = fmaf(-2.f, acc[s*4+0], zz0 + cv.x);
            acc[s*4+1] = fmaf(-2.f, acc[s*4+1], zz0 + cv.y);
            acc[s*4+2] = fmaf(-2.f, acc[s*4+2], zz1 + cv.x);
            acc[s*4+3] = fmaf(-2.f, acc[s*4+3], zz1 + cv.y);
            m0 = fminf(m0, fminf(acc[s*4+0], acc[s*4+1]));
            m1 = fminf(m1, fminf(acc[s*4+2], acc[s*4+3]));
        }
        m0 = fminf(m0, __shfl_xor_sync(0xFFFFFFFFu, m0, 1));
        m0 = fminf(m0, __shfl_xor_sync(0xFFFFFFFFu, m0, 2));
        m1 = fminf(m1, __shfl_xor_sync(0xFFFFFFFFu, m1, 1));
        m1 = fminf(m1, __shfl_xor_sync(0xFFFFFFFFu, m1, 2));
        if (q == 0) {
            g_mch[(size_t)r0 * NCHUNK + ch] = m0;
            g_mch[(size_t)r1 * NCHUNK + ch] = m1;
        }

        // pack fp16(d - min)
        uint32_t p0[8], p1[8];
#pragma unroll
        for (int s = 0; s < 8; s++) {
            p0[s] = pk_f16x2(acc[s*4+0] - m0, acc[s*4+1] - m0);
            p1[s] = pk_f16x2(acc[s*4+2] - m1, acc[s*4+3] - m1);
        }

        // staged coalesced stores: r0 group (rows row0 + w*16 + 0..7)
#pragma unroll
        for (int s = 0; s < 8; s++) stg[w][nl * 36 + q + 4 * s] = p0[s];
        __syncwarp();
        {
            const uint4* src = reinterpret_cast<const uint4*>(
                &stg[w][(l >> 2) * 36 + (l & 3) * 4]);
            uint4 v0 = src[0];
            uint4 v1 = src[4];
            uint32_t* dst = g_dh + (size_t)(row0 + w * 16 + (l >> 2)) * 512
                          + ch * 32 + (l & 3) * 4;
            *reinterpret_cast<uint4*>(dst) = v0;
            *reinterpret_cast<uint4*>(dst + 16) = v1;
        }
        __syncwarp();
        // r1 group (rows +8)
#pragma unroll
        for (int s = 0; s < 8; s++) stg[w][nl * 36 + q + 4 * s] = p1[s];
        __syncwarp();
        {
            const uint4* src = reinterpret_cast<const uint4*>(
                &stg[w][(l >> 2) * 36 + (l & 3) * 4]);
            uint4 v0 = src[0];
            uint4 v1 = src[4];
            uint32_t* dst = g_dh + (size_t)(row0 + w * 16 + 8 + (l >> 2)) * 512
                          + ch * 32 + (l & 3) * 4;
            *reinterpret_cast<uint4*>(dst) = v0;
            *reinterpret_cast<uint4*>(dst + 16) = v1;
        }
        __syncwarp();
    }
}

// ---------------------------------------------------------------------------
// k2: Z + soft_usage (half2 ex2) + exact argmin refine + counts + indices +
//     quantized gather/store + mse.  warp-per-row (16 rows/warp), grid 1024.
// ---------------------------------------------------------------------------
__global__ void __launch_bounds__(256) k2_fuse(const float* __restrict__ z,
                                               const float* __restrict__ cbk,
                                               float* __restrict__ out) {
    __shared__ float soft_s[NCODES];
    __shared__ float ws[8];
    const int tid = threadIdx.x, w = tid >> 5, l = tid & 31;
    for (int i = tid; i < NCODES; i += 256) soft_s[i] = 0.f;
    __syncthreads();

    float soft_acc[32];
#pragma unroll
    for (int i = 0; i < 32; i++) soft_acc[i] = 0.f;
    float sq_acc = 0.f;

    const int rbase = blockIdx.x * 128 + w * 16;
#pragma unroll 1
    for (int rr = 0; rr < 16; rr++) {
        const int row = rbase + rr;
        // row min from chunk mins ([row][ch] layout: coalesced 64B read)
        float mch = (l < NCHUNK) ? g_mch[(size_t)row * NCHUNK + l] : FLT_MAX;
        float m = mch;
#pragma unroll
        for (int o = 16; o > 0; o >>= 1) m = fminf(m, __shfl_xor_sync(0xFFFFFFFFu, m, o));
        const float bias = (m - mch) * L2E;

        const uint4* rp = reinterpret_cast<const uint4*>(g_dh + (size_t)row * 512);
        const float2 zrow = *reinterpret_cast<const float2*>(z + (size_t)row * DIM + 2 * l);

        float e[32];
        float Z = 0.f, lemax = 0.f;
#pragma unroll
        for (int t = 0; t < 4; t++) {
            uint4 uq = rp[l + 32 * t];
            float b = __shfl_sync(0xFFFFFFFFu, bias, (l + 32 * t) >> 3);
            uint32_t us[4] = {uq.x, uq.y, uq.z, uq.w};
#pragma unroll
            for (int p = 0; p < 4; p++) {
                __half2 h = *reinterpret_cast<__half2*>(&us[p]);
                float2 dd = __half22float2(h);
                float a0 = fmaf(-dd.x, L2E, b);
                float a1 = fmaf(-dd.y, L2E, b);
                __half2 e2 = h2exp2(__floats2half2_rn(a0, a1));   // 1 MUFU / 2 elems
                float2 ef = __half22float2(e2);
                e[t * 8 + p * 2 + 0] = ef.x;
                e[t * 8 + p * 2 + 1] = ef.y;
                Z += ef.x + ef.y;
                lemax = fmaxf(lemax, fmaxf(ef.x, ef.y));
            }
        }
        float emax = lemax;
#pragma unroll
        for (int o = 16; o > 0; o >>= 1) {
            Z += __shfl_xor_sync(0xFFFFFFFFu, Z, o);
            emax = fmaxf(emax, __shfl_xor_sync(0xFFFFFFFFu, emax, o));
        }
        const float invZ = __fdividef(1.f, Z);
#pragma unroll
        for (int i = 0; i < 32; i++) soft_acc[i] = fmaf(e[i], invZ, soft_acc[i]);

        // exact refine over all candidates within the window
        const float thr = emax * CANDF;
        float bd = FLT_MAX;
        int bc = 0x7FFFFFFF;
        unsigned bal = __ballot_sync(0xFFFFFFFFu, lemax >= thr);
        while (bal) {
            const int src = __ffs(bal) - 1;
            bal &= bal - 1;
#pragma unroll
            for (int jj = 0; jj < 32; jj++) {
                float ev = __shfl_sync(0xFFFFFFFFu, e[jj], src);
                if (ev >= thr) {
                    const int col = 8 * src + 256 * (jj >> 3) + (jj & 7);
                    float2 cv = *reinterpret_cast<const float2*>(
                        cbk + (size_t)col * DIM + 2 * l);
                    float s = fmaf(cv.x, cv.x, cv.y * cv.y)
                            - 2.f * fmaf(zrow.x, cv.x, zrow.y * cv.y);
#pragma unroll
                    for (int o = 16; o > 0; o >>= 1)
                        s += __shfl_xor_sync(0xFFFFFFFFu, s, o);
                    if (s < bd || (s == bd && col < bc)) { bd = s; bc = col; }
                }
            }
        }

        // fused: quantized gather + store + mse
        float2 cq = *reinterpret_cast<const float2*>(cbk + (size_t)bc * DIM + 2 * l);
        *reinterpret_cast<float2*>(out + OFF_Q + (size_t)row * DIM + 2 * l) = cq;
        float dx = cq.x - zrow.x, dy = cq.y - zrow.y;
        sq_acc = fmaf(dx, dx, fmaf(dy, dy, sq_acc));

        if (l == 0) {
            out[OFF_IDX + row] = (float)bc;
            atomicAdd(&g_counts[bc], 1.f);
        }
    }
#pragma unroll
    for (int jj = 0; jj < 32; jj++)
        atomicAdd(&soft_s[8 * l + 256 * (jj >> 3) + (jj & 7)], soft_acc[jj]);

#pragma unroll
    for (int o = 16; o > 0; o >>= 1) sq_acc += __shfl_xor_sync(0xFFFFFFFFu, sq_acc, o);
    if (l == 0) ws[w] = sq_acc;
    __syncthreads();
    if (tid == 0) {
        float tt = 0.f;
#pragma unroll
        for (int i = 0; i < 8; i++) tt += ws[i];
        atomicAdd(&g_sq, tt);
    }
    for (int i = tid; i < NCODES; i += 256) atomicAdd(&g_soft[i], soft_s[i]);
}

// ---------------------------------------------------------------------------
// k4: finalize scalars, usage, soft_usage, perplexity.
// ---------------------------------------------------------------------------
__global__ void __launch_bounds__(1024) k4_fin(float* __restrict__ out) {
    const int c = threadIdx.x;
    const float invN = 1.f / (float)N_ROWS;

    float usage = g_counts[c] * invN;
    out[OFF_USAGE + c] = usage;
    out[OFF_SOFT + c]  = g_soft[c] * invN;

    float term = usage * logf(usage + 1e-8f);
#pragma unroll
    for (int o = 16; o > 0; o >>= 1) term += __shfl_xor_sync(0xFFFFFFFFu, term, o);

    __shared__ float red[32];
    if ((c & 31) == 0) red[c >> 5] = term;
    __syncthreads();
    if (c == 0) {
        float sum = 0.f;
#pragma unroll
        for (int i = 0; i < 32; i++) sum += red[i];
        float mse = g_sq / (float)((size_t)N_ROWS * DIM);
        out[OFF_LOSS] = mse * 1.25f;
        out[OFF_CBL]  = mse;
        out[OFF_CML]  = mse;
        out[OFF_PERP] = expf(-sum);
    }
}

// ---------------------------------------------------------------------------
extern "C" void kernel_launch(void* const* d_in, const int* in_sizes, int n_in,
                              void* d_out, int out_size) {
    const float* z   = (const float*)d_in[0];
    const float* cbk = (const float*)d_in[1];
    float* out = (float*)d_out;
    (void)in_sizes; (void)n_in; (void)out_size;

    k0_init<<<4, 256>>>(cbk);
    k1_gemm<<<N_ROWS / MT, 256>>>(z);
    k2_fuse<<<N_ROWS / 128, 256>>>(z, cbk, out);
    k4_fin<<<1, 1024>>>(out);
}